// round 9
// baseline (speedup 1.0000x reference)
#include <cuda_runtime.h>
#include <cstdint>

#define N_NODES 100000
#define N_EDGES 1600000
#define D_EDGE  50
#define SCAN_THREADS 1024

// 1 if receivers buffer really holds int64, 0 if int32 (harness downcasts).
__device__ int g_idx_is_i64;

// CSR scratch (all __device__ globals: no allocation).
__device__ int g_count[N_NODES];       // histogram
__device__ int g_offset[N_NODES + 1];  // exclusive CSR offsets
__device__ int g_cursor[N_NODES];      // running cursors for id scatter
__device__ int g_eid[N_EDGES];         // edge ids grouped by receiver

__device__ __forceinline__ long long load_recv(const void* __restrict__ recv, int e) {
    return g_idx_is_i64 ? ((const long long*)recv)[e]
                        : (long long)((const int*)recv)[e];
}

// ---------------------------------------------------------------------------
// Kernel 1: zero counters; block 0 also detects the receivers dtype by
// interpreting the first 2048 64-bit words as int64 — true int64 indices all
// lie in [0, N_NODES); packed int32 pairs blow the range w.p. ~1.
// ---------------------------------------------------------------------------
__global__ void init_kernel(const void* __restrict__ recv) {
    if (blockIdx.x == 0) {
        const long long* p64 = (const long long*)recv;
        int bad = 0;
        for (int i = threadIdx.x; i < 2048; i += blockDim.x) {
            long long v = p64[i];
            if (v < 0 || v >= N_NODES) bad = 1;
        }
        int any_bad = __syncthreads_or(bad);
        if (threadIdx.x == 0) g_idx_is_i64 = any_bad ? 0 : 1;
    }
    for (int i = blockIdx.x * blockDim.x + threadIdx.x; i < N_NODES;
         i += gridDim.x * blockDim.x) {
        g_count[i] = 0;
    }
}

// ---------------------------------------------------------------------------
// Kernel 2: histogram of receivers (int atomics, spread over 100K addresses).
// ---------------------------------------------------------------------------
__global__ void hist_kernel(const void* __restrict__ recv) {
    int e = blockIdx.x * blockDim.x + threadIdx.x;
    if (e >= N_EDGES) return;
    long long r = load_recv(recv, e);
    if ((unsigned long long)r >= (unsigned long long)N_NODES) return;
    atomicAdd(&g_count[(int)r], 1);
}

// ---------------------------------------------------------------------------
// Kernel 3: exclusive prefix scan of g_count -> g_offset (+ cursor copy).
// Single block: per-thread serial sum over a contiguous chunk, Hillis-Steele
// block scan, then per-thread serial offset write.
// ---------------------------------------------------------------------------
__global__ void scan_kernel() {
    __shared__ int s[SCAN_THREADS];
    const int chunk = (N_NODES + SCAN_THREADS - 1) / SCAN_THREADS;  // 98
    const int t = threadIdx.x;
    const int lo = t * chunk;
    const int hi = (lo + chunk < N_NODES) ? lo + chunk : N_NODES;

    int sum = 0;
    for (int i = lo; i < hi; i++) sum += g_count[i];
    s[t] = sum;
    __syncthreads();

    // inclusive Hillis-Steele scan of s
    for (int d = 1; d < SCAN_THREADS; d <<= 1) {
        int v = (t >= d) ? s[t - d] : 0;
        __syncthreads();
        s[t] += v;
        __syncthreads();
    }

    int run = (t == 0) ? 0 : s[t - 1];
    for (int i = lo; i < hi; i++) {
        int c = g_count[i];
        g_offset[i] = run;
        g_cursor[i] = run;
        run += c;
    }
    if (t == SCAN_THREADS - 1) g_offset[N_NODES] = run;
}

// ---------------------------------------------------------------------------
// Kernel 4: scatter edge ids into CSR order.
// ---------------------------------------------------------------------------
__global__ void scatter_ids_kernel(const void* __restrict__ recv) {
    int e = blockIdx.x * blockDim.x + threadIdx.x;
    if (e >= N_EDGES) return;
    long long r = load_recv(recv, e);
    if ((unsigned long long)r >= (unsigned long long)N_NODES) return;
    int pos = atomicAdd(&g_cursor[(int)r], 1);
    g_eid[pos] = e;
}

// ---------------------------------------------------------------------------
// Kernel 5: gather. One warp per node; lanes 0..24 own float2 dim-pairs.
// Broadcast eid loads; 2-way unroll with independent accumulators for MLP.
// Writes every output row exactly once (zeros included) -> no zero pass.
// ---------------------------------------------------------------------------
__global__ void gather_kernel(const float* __restrict__ edges,
                              float* __restrict__ out) {
    const int warp = (blockIdx.x * blockDim.x + threadIdx.x) >> 5;
    const int lane = threadIdx.x & 31;
    if (warp >= N_NODES) return;

    const int beg = g_offset[warp];
    const int end = g_offset[warp + 1];

    float2 acc0 = make_float2(0.f, 0.f);
    float2 acc1 = make_float2(0.f, 0.f);
    const bool act = (lane < 25);
    const int d = 2 * lane;

    int j = beg;
    for (; j + 1 < end; j += 2) {
        int e0 = g_eid[j];
        int e1 = g_eid[j + 1];
        if (act) {
            float2 v0 = *reinterpret_cast<const float2*>(edges + (size_t)e0 * D_EDGE + d);
            float2 v1 = *reinterpret_cast<const float2*>(edges + (size_t)e1 * D_EDGE + d);
            acc0.x += v0.x; acc0.y += v0.y;
            acc1.x += v1.x; acc1.y += v1.y;
        }
    }
    if (j < end && act) {
        int e = g_eid[j];
        float2 v = *reinterpret_cast<const float2*>(edges + (size_t)e * D_EDGE + d);
        acc0.x += v.x; acc0.y += v.y;
    }

    if (act) {
        float2 r = make_float2(acc0.x + acc1.x, acc0.y + acc1.y);
        *reinterpret_cast<float2*>(out + (size_t)warp * D_EDGE + d) = r;
    }
}

extern "C" void kernel_launch(void* const* d_in, const int* in_sizes, int n_in,
                              void* d_out, int out_size) {
    // Identify inputs by element count (robust to ordering):
    //   nodes: 800,000 f32 (unused) | edges: 80,000,000 f32 | receivers: 1,600,000
    const float* edges = nullptr;
    const void* receivers = nullptr;
    for (int i = 0; i < n_in; i++) {
        if (in_sizes[i] == N_EDGES * D_EDGE) {
            edges = (const float*)d_in[i];
        } else if (in_sizes[i] == N_EDGES) {
            receivers = d_in[i];
        }
    }
    float* out = (float*)d_out;

    const int T = 256;

    // 1) zero counters + dtype detect
    init_kernel<<<392, T>>>(receivers);

    // 2) histogram
    hist_kernel<<<(N_EDGES + T - 1) / T, T>>>(receivers);

    // 3) exclusive scan -> CSR offsets
    scan_kernel<<<1, SCAN_THREADS>>>();

    // 4) scatter edge ids
    scatter_ids_kernel<<<(N_EDGES + T - 1) / T, T>>>(receivers);

    // 5) gather into output (one warp per node)
    const int warps = N_NODES;
    const int blocks = (warps * 32 + T - 1) / T;
    gather_kernel<<<blocks, T>>>(edges, out);
}

// round 10
// speedup vs baseline: 2.4715x; 2.4715x over previous
#include <cuda_runtime.h>
#include <cstdint>

#define N_NODES 100000
#define N_EDGES 1600000
#define D_EDGE  50

// 1 if receivers buffer really holds int64, 0 if int32 (harness downcasts).
__device__ int g_idx_is_i64;

// ---------------------------------------------------------------------------
// Kernel 1: fused init. Block 0 detects the receivers dtype (interpret the
// first 2048 64-bit words as int64: true int64 indices all lie in
// [0, N_NODES); packed int32 pairs blow the range w.p. ~1). All blocks zero
// the 20MB output (harness poisons it to 0xAA). d_out is 256B-aligned.
// ---------------------------------------------------------------------------
__global__ void init_kernel(const void* __restrict__ recv,
                            float4* __restrict__ out4) {
    if (blockIdx.x == 0) {
        const long long* p64 = (const long long*)recv;
        int bad = 0;
        for (int i = threadIdx.x; i < 2048; i += blockDim.x) {
            long long v = p64[i];
            if (v < 0 || v >= N_NODES) bad = 1;
        }
        int any_bad = __syncthreads_or(bad);
        if (threadIdx.x == 0) g_idx_is_i64 = any_bad ? 0 : 1;
    }
    const int n4 = N_NODES * D_EDGE / 4;  // 1,250,000 float4 (20MB)
    for (int i = blockIdx.x * blockDim.x + threadIdx.x; i < n4;
         i += gridDim.x * blockDim.x) {
        out4[i] = make_float4(0.f, 0.f, 0.f, 0.f);
    }
}

// ---------------------------------------------------------------------------
// Kernel 2: scatter-add DIRECTLY into the 200B/row output, parity-phased:
// row base byte offset r*200 == (r&1)*8 (mod 16), so
//   even r: v4 chunks at float offsets 0,4,...,44  + v2 at 48
//   odd  r: v2 at 0 + v4 chunks at float offsets 2,6,...,46
// Every v4 target is 16B-aligned, every v2 target 8B-aligned.
// One thread per (edge, chunk), 13 chunks/edge; chunk is the fast dimension
// so consecutive lanes read/atomize consecutive chunks of the same row
// (coalesced source loads, line-local red targets).
// ---------------------------------------------------------------------------
__global__ void scatter_kernel(const float* __restrict__ edges,
                               const void* __restrict__ recv,
                               float* __restrict__ out) {
    const int idx = blockIdx.x * blockDim.x + threadIdx.x;
    const int total = N_EDGES * 13;
    if (idx >= total) return;

    const int e = idx / 13;
    const int c = idx - e * 13;

    long long r;
    if (g_idx_is_i64) {
        r = ((const long long*)recv)[e];
    } else {
        r = (long long)((const int*)recv)[e];
    }
    // Safety clamp: a wrong dtype interpretation shows as rel_err, not a fault.
    if ((unsigned long long)r >= (unsigned long long)N_NODES) return;

    const float* row = edges + (size_t)e * D_EDGE;
    float* dst = out + (size_t)r * D_EDGE;
    const int odd = (int)(r & 1);

    if (c < 12) {
        const int off = 4 * c + 2 * odd;          // even -> 8B-aligned source
        float2 a = *reinterpret_cast<const float2*>(row + off);
        float2 b = *reinterpret_cast<const float2*>(row + off + 2);
        asm volatile("red.global.add.v4.f32 [%0], {%1, %2, %3, %4};"
                     :: "l"(dst + off), "f"(a.x), "f"(a.y), "f"(b.x), "f"(b.y)
                     : "memory");
    } else {
        const int off = odd ? 0 : 48;
        float2 a = *reinterpret_cast<const float2*>(row + off);
        asm volatile("red.global.add.v2.f32 [%0], {%1, %2};"
                     :: "l"(dst + off), "f"(a.x), "f"(a.y)
                     : "memory");
    }
}

extern "C" void kernel_launch(void* const* d_in, const int* in_sizes, int n_in,
                              void* d_out, int out_size) {
    // Identify inputs by element count (robust to ordering):
    //   nodes: 800,000 f32 (unused) | edges: 80,000,000 f32 | receivers: 1,600,000
    const float* edges = nullptr;
    const void* receivers = nullptr;
    for (int i = 0; i < n_in; i++) {
        if (in_sizes[i] == N_EDGES * D_EDGE) {
            edges = (const float*)d_in[i];
        } else if (in_sizes[i] == N_EDGES) {
            receivers = d_in[i];
        }
    }
    float* out = (float*)d_out;

    // 1) fused dtype-detect + zero output
    init_kernel<<<2048, 256>>>(receivers, (float4*)out);

    // 2) scatter-add straight into the output
    const int total = N_EDGES * 13;
    const int threads = 256;
    const int blocks = (total + threads - 1) / threads;
    scatter_kernel<<<blocks, threads>>>(edges, receivers, out);
}

// round 11
// speedup vs baseline: 2.4786x; 1.0029x over previous
#include <cuda_runtime.h>
#include <cstdint>

#define N_NODES 100000
#define N_EDGES 1600000
#define D_EDGE  50
#define EDGES_PER_BLOCK 128
#define SLOT 208   // bytes per staged edge row (13*16, 16B-aligned slots)

// 1 if receivers buffer really holds int64, 0 if int32 (harness downcasts).
__device__ int g_idx_is_i64;

// ---------------------------------------------------------------------------
// Kernel 1: fused init. Block 0 detects the receivers dtype (first 2048
// 64-bit words as int64: true int64 indices all in [0, N_NODES); packed int32
// pairs blow the range w.p. ~1). All blocks zero the 20MB output.
// ---------------------------------------------------------------------------
__global__ void init_kernel(const void* __restrict__ recv,
                            float4* __restrict__ out4) {
    if (blockIdx.x == 0) {
        const long long* p64 = (const long long*)recv;
        int bad = 0;
        for (int i = threadIdx.x; i < 2048; i += blockDim.x) {
            long long v = p64[i];
            if (v < 0 || v >= N_NODES) bad = 1;
        }
        int any_bad = __syncthreads_or(bad);
        if (threadIdx.x == 0) g_idx_is_i64 = any_bad ? 0 : 1;
    }
    const int n4 = N_NODES * D_EDGE / 4;  // 1,250,000 float4 (20MB)
    for (int i = blockIdx.x * blockDim.x + threadIdx.x; i < n4;
         i += gridDim.x * blockDim.x) {
        out4[i] = make_float4(0.f, 0.f, 0.f, 0.f);
    }
}

// ---------------------------------------------------------------------------
// Kernel 2: TMA bulk-reduce scatter. Each block stages 128 edge rows into
// SMEM (coalesced float2 copies, shifted 8B for odd receivers so the 192B
// bulk window is 16B-aligned on BOTH src and dst), then one thread per edge
// issues:
//   even r: cp.reduce.async.bulk 192B @ floats[0,48)  + red.v2 @ float 48
//   odd  r: red.v2 @ float 0 + cp.reduce.async.bulk 192B @ floats[2,50)
//           (dst byte addr = r*200+8 ≡ 0 mod 16 since r odd)
// This replaces 12 red.v4 lane-ops per edge (the R10 issue-floor) with a
// single TMA op. wait_group 0 before exit keeps SMEM live for TMA reads.
// ---------------------------------------------------------------------------
__global__ void scatter_bulk_kernel(const float* __restrict__ edges,
                                    const void* __restrict__ recv,
                                    float* __restrict__ out) {
    __shared__ __align__(16) char s_rows[EDGES_PER_BLOCK * SLOT];
    __shared__ int s_recv[EDGES_PER_BLOCK];

    const int tid = threadIdx.x;
    const int e_base = blockIdx.x * EDGES_PER_BLOCK;

    // --- load receivers for this batch ---
    if (tid < EDGES_PER_BLOCK) {
        const int e = e_base + tid;
        long long r;
        if (g_idx_is_i64) {
            r = ((const long long*)recv)[e];
        } else {
            r = (long long)((const int*)recv)[e];
        }
        // clamp: wrong dtype interpretation shows as rel_err, not a fault
        if ((unsigned long long)r >= (unsigned long long)N_NODES) r = 0;
        s_recv[tid] = (int)r;
    }
    __syncthreads();

    // --- stage edge rows into SMEM with parity shift ---
    // 128 edges * 25 float2 = 3200 float2; 256 threads -> 12.5 each.
    // Consecutive i -> consecutive gmem float2 (coalesced reads).
    for (int i = tid; i < EDGES_PER_BLOCK * 25; i += blockDim.x) {
        const int el = i / 25;
        const int k = i - el * 25;
        const int shift = (s_recv[el] & 1) ? 8 : 0;
        float2 v = *reinterpret_cast<const float2*>(
            edges + (size_t)(e_base + el) * D_EDGE + 2 * k);
        *reinterpret_cast<float2*>(s_rows + el * SLOT + shift + 8 * k) = v;
    }
    __syncthreads();
    // Make generic-proxy SMEM writes visible to the async (TMA) proxy.
    asm volatile("fence.proxy.async.shared::cta;" ::: "memory");

    // --- one thread per edge issues bulk reduce + 8B remainder ---
    if (tid < EDGES_PER_BLOCK) {
        const int r = s_recv[tid];
        const int odd = r & 1;
        char* slot = s_rows + tid * SLOT;
        float* dst = out + (size_t)r * D_EDGE;

        uint32_t s_bulk = (uint32_t)__cvta_generic_to_shared(slot + (odd ? 16 : 0));
        float* g_bulk = dst + (odd ? 2 : 0);
        asm volatile(
            "cp.reduce.async.bulk.global.shared::cta.bulk_group.add.f32 "
            "[%0], [%1], %2;"
            :: "l"(g_bulk), "r"(s_bulk), "r"(192) : "memory");

        // remainder: floats {48,49} (even r) or {0,1} (odd r)
        float2 rem = *reinterpret_cast<const float2*>(slot + (odd ? 8 : 192));
        float* g_rem = dst + (odd ? 0 : 48);
        asm volatile("red.global.add.v2.f32 [%0], {%1, %2};"
                     :: "l"(g_rem), "f"(rem.x), "f"(rem.y) : "memory");

        asm volatile("cp.async.bulk.commit_group;" ::: "memory");
        asm volatile("cp.async.bulk.wait_group 0;" ::: "memory");
    }
    // __syncthreads not needed: only issuing threads touched SMEM after the
    // fence, and each waited for its own bulk group before exit.
    __syncthreads();  // keep SMEM alive until ALL threads' TMA reads finish
}

extern "C" void kernel_launch(void* const* d_in, const int* in_sizes, int n_in,
                              void* d_out, int out_size) {
    // Identify inputs by element count (robust to ordering):
    //   nodes: 800,000 f32 (unused) | edges: 80,000,000 f32 | receivers: 1,600,000
    const float* edges = nullptr;
    const void* receivers = nullptr;
    for (int i = 0; i < n_in; i++) {
        if (in_sizes[i] == N_EDGES * D_EDGE) {
            edges = (const float*)d_in[i];
        } else if (in_sizes[i] == N_EDGES) {
            receivers = d_in[i];
        }
    }
    float* out = (float*)d_out;

    // 1) fused dtype-detect + zero output
    init_kernel<<<2048, 256>>>(receivers, (float4*)out);

    // 2) TMA bulk-reduce scatter (1.6M / 128 = 12500 blocks exactly)
    scatter_bulk_kernel<<<N_EDGES / EDGES_PER_BLOCK, 256>>>(edges, receivers, out);
}